// round 16
// baseline (speedup 1.0000x reference)
#include <cuda_runtime.h>
#include <cuda_fp16.h>
#include <cstdint>

// ============================================================================
// QuantizedLinear: out = scale * (x @ S^T) + bias, S = sign(w)*(|w|>0.7*mean|w|)
// x [65536, 512] fp32, w [512, 512] fp32, bias [512] fp32, out [65536, 512] fp32
//
// R16: R15 single-kernel design + in-warp software pipelining: A fragments
// double-buffered (ldsm A(ks+1) issued before mma(ks)) so the smem port and
// tensor pipe overlap instead of alternating. kt loop fully unrolled.
// GEMM: BM128/BN128/BK64, 8 warps (2Mx4N), warp 64x32, ldmatrix.x4, SW128,
// 3-stage cp.async, mma.sync.m16n8k16.f16. (compute_103: no tcgen05.)
// ============================================================================
#define K_DIM 512
#define N_DIM 512
#define M_DIM 65536
#define BM 128
#define BN 128
#define BK 64
#define KT (K_DIM / BK)      // 8
#define STAGES 3
#define THREADS 256
#define NPREP 64             // weight-prep CTAs

#define A_STAGE_BYTES (BM * BK * 2)                    // 16384
#define B_STAGE_BYTES (BN * BK * 2)                    // 16384
#define STAGE_BYTES   (A_STAGE_BYTES + B_STAGE_BYTES)  // 32768
#define SMEM_TOTAL    (STAGES * STAGE_BYTES + 128)     // 98432 -> 2 CTAs/SM

// Scratch (allocation-free __device__ globals; zero-initialized)
__device__ __half  d_xh[(size_t)M_DIM * K_DIM];        // 64 MB fp16 x
__device__ __half  d_wq[N_DIM * K_DIM];
__device__ double  d_partialW[NPREP];
__device__ float   d_scale;
__device__ int     d_flagA[NPREP];
__device__ int     d_flagQ[NPREP];
__device__ int     d_flagC[(M_DIM / BM) * 4];          // one per CTA

// ============================================================================
// Helpers
// ============================================================================
__device__ __forceinline__ uint32_t smem_u32(const void* p) {
    uint32_t a;
    asm("{ .reg .u64 t; cvta.to.shared.u64 t, %1; cvt.u32.u64 %0, t; }"
        : "=r"(a) : "l"(p));
    return a;
}

__device__ __forceinline__ void cp16(uint32_t saddr, const void* gaddr) {
    asm volatile("cp.async.cg.shared.global [%0], [%1], 16;"
                 :: "r"(saddr), "l"(gaddr) : "memory");
}

__device__ __forceinline__ void cp_commit() {
    asm volatile("cp.async.commit_group;" ::: "memory");
}

__device__ __forceinline__ void cp_wait1() {
    asm volatile("cp.async.wait_group 1;" ::: "memory");
}

__device__ __forceinline__ void ldsm_x4(uint32_t& r0, uint32_t& r1,
                                        uint32_t& r2, uint32_t& r3,
                                        uint32_t addr) {
    asm volatile("ldmatrix.sync.aligned.m8n8.x4.shared.b16 {%0,%1,%2,%3}, [%4];"
                 : "=r"(r0), "=r"(r1), "=r"(r2), "=r"(r3) : "r"(addr));
}

__device__ __forceinline__ void mma_f16(float* c, uint32_t a0, uint32_t a1,
                                        uint32_t a2, uint32_t a3,
                                        uint32_t b0, uint32_t b1) {
    asm volatile(
        "mma.sync.aligned.m16n8k16.row.col.f32.f16.f16.f32 "
        "{%0,%1,%2,%3}, {%4,%5,%6,%7}, {%8,%9}, {%0,%1,%2,%3};"
        : "+f"(c[0]), "+f"(c[1]), "+f"(c[2]), "+f"(c[3])
        : "r"(a0), "r"(a1), "r"(a2), "r"(a3), "r"(b0), "r"(b1));
}

__device__ __forceinline__ void spin_flag(int* f) {
    while (atomicAdd(f, 0) == 0) __nanosleep(64);
}

// ============================================================================
// Single fused kernel
// ============================================================================
__global__ void __launch_bounds__(THREADS, 2) gemm_f16(
    const float* __restrict__ x,
    const float* __restrict__ w,
    const float* __restrict__ bias,
    float* __restrict__ out)
{
    extern __shared__ char smem[];
    __shared__ double sred[THREADS];
    __shared__ float s_thresh;
    const uint32_t sb = (smem_u32(smem) + 127u) & ~127u;
    const int tid = threadIdx.x;
    const int bid = blockIdx.x;
    const int wid = tid >> 5;
    const int lane = tid & 31;
    const int grp = lane >> 2;
    const int qc = lane & 3;

    const int ntile = bid & 3;              // bids 4m..4m+3 share M-tile m
    const int mtile = bid >> 2;
    const int m0 = mtile * BM;
    const int n0 = ntile * BN;

    // ======== Weight prep (bids 0..63): abssum -> scale -> quant ========
    if (bid < NPREP) {
        const float4* wp = reinterpret_cast<const float4*>(w) + bid * 1024;
        double a = 0.0;
        #pragma unroll
        for (int i = 0; i < 4; i++) {
            const float4 v = wp[tid + i * THREADS];
            a += (double)fabsf(v.x) + (double)fabsf(v.y) +
                 (double)fabsf(v.z) + (double)fabsf(v.w);
        }
        sred[tid] = a;
        __syncthreads();
        for (int o = 128; o > 0; o >>= 1) {
            if (tid < o) sred[tid] += sred[tid + o];
            __syncthreads();
        }
        if (tid == 0) {
            d_partialW[bid] = sred[0];
            __threadfence();
            atomicExch(&d_flagA[bid], 1);
        }
        if (tid < NPREP) spin_flag(&d_flagA[tid]);
        __syncthreads();
        __threadfence();
        if (tid == 0) {
            double tot = 0.0;
            for (int i = 0; i < NPREP; i++) tot += d_partialW[i];  // fixed order
            float sc = (float)(tot / (double)(N_DIM * K_DIM));
            if (sc < 1e-8f) sc = 1e-8f;
            s_thresh = 0.7f * sc;
            if (bid == 0) d_scale = sc;
        }
        __syncthreads();
        const float th = s_thresh;
        const float* ws = w + bid * 4096;
        __half* qs = d_wq + bid * 4096;
        #pragma unroll
        for (int i = 0; i < 16; i++) {
            const float v = ws[tid + i * THREADS];
            const float q = (fabsf(v) > th) ? (v > 0.0f ? 1.0f : -1.0f) : 0.0f;
            qs[tid + i * THREADS] = __float2half_rn(q);
        }
        __threadfence();
        __syncthreads();
        if (tid == 0) atomicExch(&d_flagQ[bid], 1);
    }

    // ======== x -> fp16: every CTA converts its own quarter (32 rows) ========
    {
        const int r0 = m0 + ntile * 32;
        const float4* src = reinterpret_cast<const float4*>(x + (size_t)r0 * K_DIM);
        uint2* dst = reinterpret_cast<uint2*>(d_xh + (size_t)r0 * K_DIM);
        #pragma unroll 8
        for (int i = tid; i < 32 * K_DIM / 4; i += THREADS) {   // 4096 float4
            const float4 v = src[i];
            __half2 h0 = __floats2half2_rn(v.x, v.y);
            __half2 h1 = __floats2half2_rn(v.z, v.w);
            uint2 o;
            o.x = *reinterpret_cast<const uint32_t*>(&h0);
            o.y = *reinterpret_cast<const uint32_t*>(&h1);
            dst[i] = o;
        }
        __threadfence();
        __syncthreads();
        if (tid == 0) atomicExch(&d_flagC[bid], 1);
    }

    // ======== gates: flagQ[0..63] (B + scale), flagC siblings (A) ========
    if (tid < NPREP) spin_flag(&d_flagQ[tid]);
    else if (tid < NPREP + 4) spin_flag(&d_flagC[(mtile << 2) + (tid - NPREP)]);
    __syncthreads();
    __threadfence();

    // ======== GEMM ========
    const int warp_m = (wid & 1) * 64;
    const int warp_n = (wid >> 1) * 32;
    const __half* xh = d_xh;
    const __half* wq = d_wq;

    auto load_stage = [&](int s, int kt) {
        const uint32_t sA = sb + s * STAGE_BYTES;
        const uint32_t sB = sA + A_STAGE_BYTES;
        const int kk = kt * BK;
        #pragma unroll
        for (int i = 0; i < 4; i++) {
            int c_lin = tid + i * THREADS;
            int row = c_lin >> 3, c = c_lin & 7;
            cp16(sA + (uint32_t)row * 128 + (uint32_t)((c ^ (row & 7)) << 4),
                 xh + (size_t)(m0 + row) * K_DIM + kk + c * 8);
        }
        #pragma unroll
        for (int i = 0; i < 4; i++) {
            int c_lin = tid + i * THREADS;
            int row = c_lin >> 3, c = c_lin & 7;
            cp16(sB + (uint32_t)row * 128 + (uint32_t)((c ^ (row & 7)) << 4),
                 wq + (size_t)(n0 + row) * K_DIM + kk + c * 8);
        }
    };

    const int lt = lane >> 3;
    const int lr = lane & 7;
    uint32_t baseA[4], baseB[2];
    {
        const int rowoffA = (lt & 1) * 8;
        const int khA = lt >> 1;
        #pragma unroll
        for (int tm = 0; tm < 4; tm++) {
            int row = warp_m + tm * 16 + rowoffA + lr;
            baseA[tm] = (uint32_t)row * 128 + (uint32_t)((khA ^ lr) << 4);
        }
        const int rowoffB = (lt >> 1) * 8;
        const int khB = lt & 1;
        #pragma unroll
        for (int tnp = 0; tnp < 2; tnp++) {
            int row = warp_n + tnp * 16 + rowoffB + lr;
            baseB[tnp] = (uint32_t)A_STAGE_BYTES +
                         (uint32_t)row * 128 + (uint32_t)((khB ^ lr) << 4);
        }
    }

    float acc[4][4][4];
    #pragma unroll
    for (int i = 0; i < 4; i++)
        #pragma unroll
        for (int j = 0; j < 4; j++)
            #pragma unroll
            for (int r = 0; r < 4; r++) acc[i][j][r] = 0.0f;

    load_stage(0, 0);
    cp_commit();
    load_stage(1, 1);
    cp_commit();

    // A-fragment double buffer: aF[cur] consumed while aF[nxt] is loaded
    uint32_t aF[2][4][4];

    #pragma unroll
    for (int kt = 0; kt < KT; kt++) {
        cp_wait1();                 // committed = 2+kt; <=1 pending => kt done
        __syncthreads();            // stage kt visible; slot (kt+2)%3 free

        if (kt + 2 < KT) load_stage((kt + 2) % STAGES, kt + 2);
        cp_commit();

        const uint32_t sStage = sb + (uint32_t)(kt % STAGES) * STAGE_BYTES;

        // prime A fragments for ks=0
        #pragma unroll
        for (int tm = 0; tm < 4; tm++)
            ldsm_x4(aF[0][tm][0], aF[0][tm][1], aF[0][tm][2], aF[0][tm][3],
                    sStage + baseA[tm]);

        #pragma unroll
        for (int ks = 0; ks < 4; ks++) {
            const int cur = ks & 1, nxt = cur ^ 1;
            const uint32_t kx = (uint32_t)ks << 5;

            // B just-in-time for this ks
            uint32_t b[4][2];
            ldsm_x4(b[0][0], b[0][1], b[1][0], b[1][1], (sStage + baseB[0]) ^ kx);
            ldsm_x4(b[2][0], b[2][1], b[3][0], b[3][1], (sStage + baseB[1]) ^ kx);

            // prefetch A for ks+1 (hidden under the mma stream below)
            if (ks < 3) {
                const uint32_t kxn = (uint32_t)(ks + 1) << 5;
                #pragma unroll
                for (int tm = 0; tm < 4; tm++)
                    ldsm_x4(aF[nxt][tm][0], aF[nxt][tm][1],
                            aF[nxt][tm][2], aF[nxt][tm][3],
                            (sStage + baseA[tm]) ^ kxn);
            }

            #pragma unroll
            for (int tm = 0; tm < 4; tm++)
                #pragma unroll
                for (int tn = 0; tn < 4; tn++)
                    mma_f16(acc[tm][tn],
                            aF[cur][tm][0], aF[cur][tm][1],
                            aF[cur][tm][2], aF[cur][tm][3],
                            b[tn][0], b[tn][1]);
        }
    }

    // ---- Epilogue: out = scale*acc + bias ----
    const float scale = d_scale;
    #pragma unroll
    for (int tm = 0; tm < 4; tm++) {
        #pragma unroll
        for (int tn = 0; tn < 4; tn++) {
            const int row = m0 + warp_m + tm * 16 + grp;
            const int col = n0 + warp_n + tn * 8 + qc * 2;
            const float2 bv = *reinterpret_cast<const float2*>(bias + col);
            float2 v0, v1;
            v0.x = fmaf(scale, acc[tm][tn][0], bv.x);
            v0.y = fmaf(scale, acc[tm][tn][1], bv.y);
            v1.x = fmaf(scale, acc[tm][tn][2], bv.x);
            v1.y = fmaf(scale, acc[tm][tn][3], bv.y);
            *reinterpret_cast<float2*>(out + (size_t)row * N_DIM + col) = v0;
            *reinterpret_cast<float2*>(out + (size_t)(row + 8) * N_DIM + col) = v1;
        }
    }
}

// ============================================================================
// Host: ONE launch
// ============================================================================
extern "C" void kernel_launch(void* const* d_in, const int* in_sizes, int n_in,
                              void* d_out, int out_size) {
    const float* x    = (const float*)d_in[0];
    const float* w    = (const float*)d_in[1];
    const float* bias = (const float*)d_in[2];
    float* out        = (float*)d_out;
    const int M = in_sizes[0] / K_DIM;   // 65536

    cudaFuncSetAttribute(gemm_f16, cudaFuncAttributeMaxDynamicSharedMemorySize,
                         SMEM_TOTAL);

    const int grid = (M / BM) * (N_DIM / BN);   // 512 * 4 = 2048
    gemm_f16<<<grid, THREADS, SMEM_TOTAL>>>(x, w, bias, out);
}

// round 17
// speedup vs baseline: 1.0746x; 1.0746x over previous
#include <cuda_runtime.h>
#include <cuda_fp16.h>
#include <cstdint>

// ============================================================================
// QuantizedLinear: out = scale * (x @ S^T) + bias, S = sign(w)*(|w|>0.7*mean|w|)
// x [65536, 512] fp32, w [512, 512] fp32, bias [512] fp32, out [65536, 512] fp32
//
// R17: R15 single-kernel flag design + CUTLASS-shape GEMM core:
// block 128x128, 4 warps (2Mx2N), warp tile 64x64 (acc=128 regs, ~200 regs),
// 128 threads, ldsm/mma = 0.25, 16-deep independent mma ILP.
// 3-stage cp.async, ldmatrix.x4, SW128, mma.sync.m16n8k16.f16.
// ============================================================================
#define K_DIM 512
#define N_DIM 512
#define M_DIM 65536
#define BM 128
#define BN 128
#define BK 64
#define KT (K_DIM / BK)      // 8
#define STAGES 3
#define THREADS 128
#define NPREP 64

#define A_STAGE_BYTES (BM * BK * 2)                    // 16384
#define B_STAGE_BYTES (BN * BK * 2)                    // 16384
#define STAGE_BYTES   (A_STAGE_BYTES + B_STAGE_BYTES)  // 32768
#define SMEM_TOTAL    (STAGES * STAGE_BYTES + 128)     // 98432 -> 2 CTAs/SM

// Scratch (allocation-free __device__ globals; zero-initialized)
__device__ __half  d_xh[(size_t)M_DIM * K_DIM];
__device__ __half  d_wq[N_DIM * K_DIM];
__device__ double  d_partialW[NPREP];
__device__ float   d_scale;
__device__ int     d_flagA[NPREP];
__device__ int     d_flagQ[NPREP];
__device__ int     d_flagC[(M_DIM / BM) * 4];

// ============================================================================
// Helpers
// ============================================================================
__device__ __forceinline__ uint32_t smem_u32(const void* p) {
    uint32_t a;
    asm("{ .reg .u64 t; cvta.to.shared.u64 t, %1; cvt.u32.u64 %0, t; }"
        : "=r"(a) : "l"(p));
    return a;
}

__device__ __forceinline__ void cp16(uint32_t saddr, const void* gaddr) {
    asm volatile("cp.async.cg.shared.global [%0], [%1], 16;"
                 :: "r"(saddr), "l"(gaddr) : "memory");
}

__device__ __forceinline__ void cp_commit() {
    asm volatile("cp.async.commit_group;" ::: "memory");
}

__device__ __forceinline__ void cp_wait1() {
    asm volatile("cp.async.wait_group 1;" ::: "memory");
}

__device__ __forceinline__ void ldsm_x4(uint32_t& r0, uint32_t& r1,
                                        uint32_t& r2, uint32_t& r3,
                                        uint32_t addr) {
    asm volatile("ldmatrix.sync.aligned.m8n8.x4.shared.b16 {%0,%1,%2,%3}, [%4];"
                 : "=r"(r0), "=r"(r1), "=r"(r2), "=r"(r3) : "r"(addr));
}

__device__ __forceinline__ void mma_f16(float* c, uint32_t a0, uint32_t a1,
                                        uint32_t a2, uint32_t a3,
                                        uint32_t b0, uint32_t b1) {
    asm volatile(
        "mma.sync.aligned.m16n8k16.row.col.f32.f16.f16.f32 "
        "{%0,%1,%2,%3}, {%4,%5,%6,%7}, {%8,%9}, {%0,%1,%2,%3};"
        : "+f"(c[0]), "+f"(c[1]), "+f"(c[2]), "+f"(c[3])
        : "r"(a0), "r"(a1), "r"(a2), "r"(a3), "r"(b0), "r"(b1));
}

__device__ __forceinline__ void spin_flag(int* f) {
    while (atomicAdd(f, 0) == 0) __nanosleep(64);
}

// ============================================================================
// Single fused kernel
// ============================================================================
__global__ void __launch_bounds__(THREADS, 2) gemm_f16(
    const float* __restrict__ x,
    const float* __restrict__ w,
    const float* __restrict__ bias,
    float* __restrict__ out)
{
    extern __shared__ char smem[];
    __shared__ double sred[THREADS];
    __shared__ float s_thresh;
    const uint32_t sb = (smem_u32(smem) + 127u) & ~127u;
    const int tid = threadIdx.x;
    const int bid = blockIdx.x;
    const int wid = tid >> 5;
    const int lane = tid & 31;
    const int grp = lane >> 2;
    const int qc = lane & 3;

    const int ntile = bid & 3;              // bids 4m..4m+3 share M-tile m
    const int mtile = bid >> 2;
    const int m0 = mtile * BM;
    const int n0 = ntile * BN;

    // ======== Weight prep (bids 0..63): abssum -> scale -> quant ========
    if (bid < NPREP) {
        const float4* wp = reinterpret_cast<const float4*>(w) + bid * 1024;
        double a = 0.0;
        #pragma unroll
        for (int i = 0; i < 8; i++) {
            const float4 v = wp[tid + i * THREADS];
            a += (double)fabsf(v.x) + (double)fabsf(v.y) +
                 (double)fabsf(v.z) + (double)fabsf(v.w);
        }
        sred[tid] = a;
        __syncthreads();
        for (int o = 64; o > 0; o >>= 1) {
            if (tid < o) sred[tid] += sred[tid + o];
            __syncthreads();
        }
        if (tid == 0) {
            d_partialW[bid] = sred[0];
            __threadfence();
            atomicExch(&d_flagA[bid], 1);
        }
        if (tid < NPREP) spin_flag(&d_flagA[tid]);
        __syncthreads();
        __threadfence();
        if (tid == 0) {
            double tot = 0.0;
            for (int i = 0; i < NPREP; i++) tot += d_partialW[i];  // fixed order
            float sc = (float)(tot / (double)(N_DIM * K_DIM));
            if (sc < 1e-8f) sc = 1e-8f;
            s_thresh = 0.7f * sc;
            if (bid == 0) d_scale = sc;
        }
        __syncthreads();
        const float th = s_thresh;
        const float* ws = w + bid * 4096;
        __half* qs = d_wq + bid * 4096;
        #pragma unroll
        for (int i = 0; i < 32; i++) {
            const float v = ws[tid + i * THREADS];
            const float q = (fabsf(v) > th) ? (v > 0.0f ? 1.0f : -1.0f) : 0.0f;
            qs[tid + i * THREADS] = __float2half_rn(q);
        }
        __threadfence();
        __syncthreads();
        if (tid == 0) atomicExch(&d_flagQ[bid], 1);
    }

    // ======== x -> fp16: every CTA converts its own quarter (32 rows) ========
    {
        const int r0 = m0 + ntile * 32;
        const float4* src = reinterpret_cast<const float4*>(x + (size_t)r0 * K_DIM);
        uint2* dst = reinterpret_cast<uint2*>(d_xh + (size_t)r0 * K_DIM);
        #pragma unroll 8
        for (int i = tid; i < 32 * K_DIM / 4; i += THREADS) {   // 4096 float4
            const float4 v = src[i];
            __half2 h0 = __floats2half2_rn(v.x, v.y);
            __half2 h1 = __floats2half2_rn(v.z, v.w);
            uint2 o;
            o.x = *reinterpret_cast<const uint32_t*>(&h0);
            o.y = *reinterpret_cast<const uint32_t*>(&h1);
            dst[i] = o;
        }
        __threadfence();
        __syncthreads();
        if (tid == 0) atomicExch(&d_flagC[bid], 1);
    }

    // ======== gates: flagQ[0..63] (B + scale), flagC siblings (A) ========
    if (tid < NPREP) spin_flag(&d_flagQ[tid]);
    else if (tid < NPREP + 4) spin_flag(&d_flagC[(mtile << 2) + (tid - NPREP)]);
    __syncthreads();
    __threadfence();

    // ======== GEMM: 4 warps, warp tile 64x64 ========
    const int warp_m = (wid & 1) * 64;      // 2 warps along M
    const int warp_n = (wid >> 1) * 64;     // 2 warps along N
    const __half* xh = d_xh;
    const __half* wq = d_wq;

    // loader: A 1024 + B 1024 chunks over 128 threads = 8+8 each
    auto load_stage = [&](int s, int kt) {
        const uint32_t sA = sb + s * STAGE_BYTES;
        const uint32_t sB = sA + A_STAGE_BYTES;
        const int kk = kt * BK;
        #pragma unroll
        for (int i = 0; i < 8; i++) {
            int c_lin = tid + i * THREADS;
            int row = c_lin >> 3, c = c_lin & 7;
            cp16(sA + (uint32_t)row * 128 + (uint32_t)((c ^ (row & 7)) << 4),
                 xh + (size_t)(m0 + row) * K_DIM + kk + c * 8);
        }
        #pragma unroll
        for (int i = 0; i < 8; i++) {
            int c_lin = tid + i * THREADS;
            int row = c_lin >> 3, c = c_lin & 7;
            cp16(sB + (uint32_t)row * 128 + (uint32_t)((c ^ (row & 7)) << 4),
                 wq + (size_t)(n0 + row) * K_DIM + kk + c * 8);
        }
    };

    // ldmatrix per-lane base addresses
    const int lt = lane >> 3;
    const int lr = lane & 7;
    uint32_t baseA[4], baseB[4];
    {
        const int rowoffA = (lt & 1) * 8;
        const int khA = lt >> 1;
        #pragma unroll
        for (int tm = 0; tm < 4; tm++) {
            int row = warp_m + tm * 16 + rowoffA + lr;
            baseA[tm] = (uint32_t)row * 128 + (uint32_t)((khA ^ lr) << 4);
        }
        const int rowoffB = (lt >> 1) * 8;
        const int khB = lt & 1;
        #pragma unroll
        for (int tnp = 0; tnp < 4; tnp++) {
            int row = warp_n + tnp * 16 + rowoffB + lr;
            baseB[tnp] = (uint32_t)A_STAGE_BYTES +
                         (uint32_t)row * 128 + (uint32_t)((khB ^ lr) << 4);
        }
    }

    float acc[4][8][4];                     // 128 registers
    #pragma unroll
    for (int i = 0; i < 4; i++)
        #pragma unroll
        for (int j = 0; j < 8; j++)
            #pragma unroll
            for (int r = 0; r < 4; r++) acc[i][j][r] = 0.0f;

    load_stage(0, 0);
    cp_commit();
    load_stage(1, 1);
    cp_commit();

    for (int kt = 0; kt < KT; kt++) {
        cp_wait1();                 // committed = 2+kt; <=1 pending => kt done
        __syncthreads();

        if (kt + 2 < KT) load_stage((kt + 2) % STAGES, kt + 2);
        cp_commit();

        const uint32_t sStage = sb + (uint32_t)(kt % STAGES) * STAGE_BYTES;

        #pragma unroll
        for (int ks = 0; ks < 4; ks++) {
            const uint32_t kx = (uint32_t)ks << 5;
            uint32_t a[4][4];
            #pragma unroll
            for (int tm = 0; tm < 4; tm++)
                ldsm_x4(a[tm][0], a[tm][1], a[tm][2], a[tm][3],
                        (sStage + baseA[tm]) ^ kx);
            uint32_t b[8][2];
            #pragma unroll
            for (int tnp = 0; tnp < 4; tnp++)
                ldsm_x4(b[2 * tnp][0], b[2 * tnp][1],
                        b[2 * tnp + 1][0], b[2 * tnp + 1][1],
                        (sStage + baseB[tnp]) ^ kx);
            #pragma unroll
            for (int tm = 0; tm < 4; tm++)
                #pragma unroll
                for (int tn = 0; tn < 8; tn++)
                    mma_f16(acc[tm][tn], a[tm][0], a[tm][1], a[tm][2], a[tm][3],
                            b[tn][0], b[tn][1]);
        }
    }

    // ---- Epilogue: out = scale*acc + bias ----
    const float scale = d_scale;
    #pragma unroll
    for (int tm = 0; tm < 4; tm++) {
        #pragma unroll
        for (int tn = 0; tn < 8; tn++) {
            const int row = m0 + warp_m + tm * 16 + grp;
            const int col = n0 + warp_n + tn * 8 + qc * 2;
            const float2 bv = *reinterpret_cast<const float2*>(bias + col);
            float2 v0, v1;
            v0.x = fmaf(scale, acc[tm][tn][0], bv.x);
            v0.y = fmaf(scale, acc[tm][tn][1], bv.y);
            v1.x = fmaf(scale, acc[tm][tn][2], bv.x);
            v1.y = fmaf(scale, acc[tm][tn][3], bv.y);
            *reinterpret_cast<float2*>(out + (size_t)row * N_DIM + col) = v0;
            *reinterpret_cast<float2*>(out + (size_t)(row + 8) * N_DIM + col) = v1;
        }
    }
}

// ============================================================================
// Host: ONE launch
// ============================================================================
extern "C" void kernel_launch(void* const* d_in, const int* in_sizes, int n_in,
                              void* d_out, int out_size) {
    const float* x    = (const float*)d_in[0];
    const float* w    = (const float*)d_in[1];
    const float* bias = (const float*)d_in[2];
    float* out        = (float*)d_out;
    const int M = in_sizes[0] / K_DIM;   // 65536

    cudaFuncSetAttribute(gemm_f16, cudaFuncAttributeMaxDynamicSharedMemorySize,
                         SMEM_TOTAL);

    const int grid = (M / BM) * (N_DIM / BN);   // 2048
    gemm_f16<<<grid, THREADS, SMEM_TOTAL>>>(x, w, bias, out);
}